// round 1
// baseline (speedup 1.0000x reference)
#include <cuda_runtime.h>

// SiteWiseLSTM on GB300 (sm_103a)
// 2-layer LSTM encoder (L=168) + autoregressive decoder (horizon=24)
// N = 32*512 = 16384 independent sequences, H=64, D=1, fp32.
//
// Strategy: 1024 blocks x 256 threads, M=16 samples per block.
//  - Thread j (0..255) owns gate row j of the 4H=256 gate vector.
//  - All weights live in SMEM, transposed (k-major) with a (j+k)&255 column
//    swizzle so both the transpose-store and the compute-load are bank-conflict
//    free.
//  - h/c state lives in SMEM as [k][m] (m contiguous) so 16 samples are read
//    with 4x LDS.128 broadcasts per k.
//  - Sample pairs are packed into f32x2 and accumulated with fma.rn.f32x2
//    (2x fp32 FMA throughput on Blackwell).
//  - Activations: exp2-based sigmoid/tanh (full fp32 accuracy, no tanh.approx).

#define TH      256     // threads per block (= 4H gate rows)
#define MM      16      // samples per block
#define HID     64
#define GATES   256     // 4*HID
#define LL      168     // encoder length
#define HORIZON 24
#define SS      512     // S
#define NBLOCKS 1024    // 16384 / MM

typedef unsigned long long u64t;

__device__ __forceinline__ u64t pk2(float a, float b) {
    u64t r;
    asm("mov.b64 %0, {%1, %2};" : "=l"(r) : "f"(a), "f"(b));
    return r;
}
__device__ __forceinline__ void upk2(u64t v, float& a, float& b) {
    asm("mov.b64 {%0, %1}, %2;" : "=f"(a), "=f"(b) : "l"(v));
}
__device__ __forceinline__ void fma2(u64t& d, u64t a, u64t b) {
    asm("fma.rn.f32x2 %0, %1, %2, %0;" : "+l"(d) : "l"(a), "l"(b));
}

__device__ __forceinline__ float sigf(float x) {
    return __fdividef(1.f, 1.f + __expf(-x));
}
__device__ __forceinline__ float tanhf_(float x) {
    // 1 - 2/(e^{2x}+1); robust at +-inf, ~1e-7 abs error
    return 1.f - __fdividef(2.f, __expf(2.f * x) + 1.f);
}

// Accumulate acc[0..7] (8 f32x2 pairs = 16 samples) += W[:, k] outer rows.
// W row r lives at Ws[r*GATES + ((j+r)&255)], h row k lives at hbase + k*MM.
__device__ __forceinline__ void mat_accum(const float* __restrict__ Ws,
                                          const float* __restrict__ hbase,
                                          int nk, int j, u64t acc[8]) {
#pragma unroll 4
    for (int k = 0; k < nk; ++k) {
        float w = Ws[k * GATES + ((j + k) & 255)];
        u64t w2 = pk2(w, w);
        const ulonglong2* hr = (const ulonglong2*)(hbase + k * MM);
        ulonglong2 a = hr[0], b = hr[1];
        fma2(acc[0], a.x, w2); fma2(acc[1], a.y, w2);
        fma2(acc[2], b.x, w2); fma2(acc[3], b.y, w2);
        a = hr[2]; b = hr[3];
        fma2(acc[4], a.x, w2); fma2(acc[5], a.y, w2);
        fma2(acc[6], b.x, w2); fma2(acc[7], b.y, w2);
    }
}

__device__ __forceinline__ void store_gates(float* __restrict__ gbuf, int j, u64t acc[8]) {
#pragma unroll
    for (int p = 0; p < 8; ++p) {
        float a, b;
        upk2(acc[p], a, b);
        gbuf[j * 17 + 2 * p]     = a;
        gbuf[j * 17 + 2 * p + 1] = b;
    }
}

// LSTM cell pointwise update for 64x16 states, distributed over 256 threads.
__device__ __forceinline__ void cell_update(const float* __restrict__ gbuf,
                                            float* __restrict__ cs,
                                            float* __restrict__ hdst, int tid) {
#pragma unroll
    for (int q = 0; q < 4; ++q) {
        int idx = tid + q * TH;          // 0..1023
        int k = idx >> 4, m = idx & 15;
        float gi = gbuf[k * 17 + m];
        float gf = gbuf[(k + 64) * 17 + m];
        float gg = gbuf[(k + 128) * 17 + m];
        float go = gbuf[(k + 192) * 17 + m];
        float c  = cs[idx];
        float nc = sigf(gf) * c + sigf(gi) * tanhf_(gg);
        cs[idx]   = nc;
        hdst[idx] = sigf(go) * tanhf_(nc);
    }
}

__global__ void __launch_bounds__(TH, 1)
sitewise_lstm_kernel(const float* __restrict__ X,
                     const float* __restrict__ Wih0, const float* __restrict__ Whh0,
                     const float* __restrict__ bih0, const float* __restrict__ bhh0,
                     const float* __restrict__ Wih1, const float* __restrict__ Whh1,
                     const float* __restrict__ bih1, const float* __restrict__ bhh1,
                     const float* __restrict__ Wcih, const float* __restrict__ Wchh,
                     const float* __restrict__ bcih, const float* __restrict__ bchh,
                     const float* __restrict__ Wout, const float* __restrict__ bout,
                     float* __restrict__ out) {
    extern __shared__ float sm[];
    float* W0s   = sm;                       // 64*256      (layer0 Whh, later decoder Wchh)
    float* W1s   = W0s + HID * GATES;        // 128*256     ([Wih1;Whh1] concat)
    float* hs    = W1s + 2 * HID * GATES;    // 128*16      (rows 0..63 h0, 64..127 h1)
    float* c0s   = hs + 2 * HID * MM;        // 64*16
    float* c1s   = c0s + HID * MM;           // 64*16
    float* gbuf  = c1s + HID * MM;           // 256*17 (padded)
    float* xs    = gbuf + GATES * 17;        // 16
    float* wouts = xs + MM;                  // 64

    const int tid = threadIdx.x;
    const int j = tid;

    // ---- load weights into SMEM, transposed + swizzled ----
    for (int idx = tid; idx < GATES * HID; idx += TH) {
        int jj = idx >> 6, k = idx & 63;     // global row jj, col k (coalesced reads)
        W0s[k * GATES + ((jj + k) & 255)]                 = Whh0[idx];
        W1s[k * GATES + ((jj + k) & 255)]                 = Wih1[idx];
        W1s[(HID + k) * GATES + ((jj + HID + k) & 255)]   = Whh1[idx];
    }
    for (int idx = tid; idx < 2 * HID * MM; idx += TH) hs[idx] = 0.f;
    for (int idx = tid; idx < HID * MM; idx += TH) { c0s[idx] = 0.f; c1s[idx] = 0.f; }
    if (tid < HID) wouts[tid] = Wout[tid];

    const float wih0j = Wih0[j];                    // (4H, 1)
    const float b0j   = bih0[j] + bhh0[j];
    const float b1j   = bih1[j] + bhh1[j];

    const int n0   = blockIdx.x * MM;               // first sample of this block
    const int xoff = (n0 >> 9) * (LL * SS) + (n0 & (SS - 1));

    __syncthreads();

    // ================= encoder: 168 steps, 2 fused layers =================
    for (int t = 0; t < LL; ++t) {
        if (tid < MM) xs[tid] = X[xoff + t * SS + tid];
        __syncthreads();

        // ---- layer 0 gates: g0 = x*wih0 + b0 + h0 @ Whh0^T ----
        u64t acc[8];
#pragma unroll
        for (int p = 0; p < 8; ++p)
            acc[p] = pk2(fmaf(xs[2 * p], wih0j, b0j),
                         fmaf(xs[2 * p + 1], wih0j, b0j));
        mat_accum(W0s, hs, HID, j, acc);
        store_gates(gbuf, j, acc);
        __syncthreads();

        cell_update(gbuf, c0s, hs, tid);            // writes new h0 (rows 0..63)
        __syncthreads();

        // ---- layer 1 gates: g1 = [y1;h1] @ [Wih1;Whh1]^T + b1 ----
#pragma unroll
        for (int p = 0; p < 8; ++p) acc[p] = pk2(b1j, b1j);
        mat_accum(W1s, hs, 2 * HID, j, acc);
        store_gates(gbuf, j, acc);
        __syncthreads();

        cell_update(gbuf, c1s, hs + HID * MM, tid); // writes new h1 (rows 64..127)
        __syncthreads();
    }

    // ================= decoder: 24 autoregressive steps =================
    // xs currently holds x[:, L-1] == x_cur. Overwrite W0s with Wchh.
    for (int idx = tid; idx < GATES * HID; idx += TH) {
        int jj = idx >> 6, k = idx & 63;
        W0s[k * GATES + ((jj + k) & 255)] = Wchh[idx];
    }
    const float wcij = Wcih[j];
    const float bcj  = bcih[j] + bchh[j];
    const float bo   = bout[0];
    __syncthreads();

    for (int t = 0; t < HORIZON; ++t) {
        u64t acc[8];
#pragma unroll
        for (int p = 0; p < 8; ++p)
            acc[p] = pk2(fmaf(xs[2 * p], wcij, bcj),
                         fmaf(xs[2 * p + 1], wcij, bcj));
        mat_accum(W0s, hs + HID * MM, HID, j, acc); // h = h1 state
        store_gates(gbuf, j, acc);
        __syncthreads();

        cell_update(gbuf, c1s, hs + HID * MM, tid);
        __syncthreads();

        // output head: y = h @ Wout^T + b_out; y feeds back as next x
        if (tid < MM) {
            float y = bo;
#pragma unroll 8
            for (int k = 0; k < HID; ++k)
                y = fmaf(wouts[k], hs[(HID + k) * MM + tid], y);
            int n = n0 + tid;
            out[((n >> 9) * HORIZON + t) * SS + (n & (SS - 1))] = y;
            xs[tid] = y;
        }
        __syncthreads();
    }
}

extern "C" void kernel_launch(void* const* d_in, const int* in_sizes, int n_in,
                              void* d_out, int out_size) {
    const float* X    = (const float*)d_in[0];
    const float* Wih0 = (const float*)d_in[1];
    const float* Whh0 = (const float*)d_in[2];
    const float* bih0 = (const float*)d_in[3];
    const float* bhh0 = (const float*)d_in[4];
    const float* Wih1 = (const float*)d_in[5];
    const float* Whh1 = (const float*)d_in[6];
    const float* bih1 = (const float*)d_in[7];
    const float* bhh1 = (const float*)d_in[8];
    const float* Wcih = (const float*)d_in[9];
    const float* Wchh = (const float*)d_in[10];
    const float* bcih = (const float*)d_in[11];
    const float* bchh = (const float*)d_in[12];
    const float* Wout = (const float*)d_in[13];
    const float* bout = (const float*)d_in[14];
    // d_in[15] = horizon (always 24; compiled in)

    const int smem_bytes = (HID * GATES + 2 * HID * GATES   // W0s, W1s
                            + 2 * HID * MM                  // hs
                            + 2 * HID * MM                  // c0s, c1s
                            + GATES * 17                    // gbuf (padded)
                            + MM + HID) * (int)sizeof(float);  // xs, wouts

    cudaFuncSetAttribute(sitewise_lstm_kernel,
                         cudaFuncAttributeMaxDynamicSharedMemorySize, smem_bytes);

    sitewise_lstm_kernel<<<NBLOCKS, TH, smem_bytes>>>(
        X, Wih0, Whh0, bih0, bhh0, Wih1, Whh1, bih1, bhh1,
        Wcih, Wchh, bcih, bchh, Wout, bout, (float*)d_out);
}

// round 2
// speedup vs baseline: 1.4758x; 1.4758x over previous
#include <cuda_runtime.h>

// SiteWiseLSTM on GB300 (sm_103a) — round 2
// 2-layer LSTM encoder (L=168) + autoregressive decoder (horizon=24)
// N = 32*512 = 16384 independent sequences, H=64, D=1, fp32.
//
// Round-2 design (vs round 1):
//  - 4x4 register tile: thread (unit r, sample-group mg) computes the 4 gates
//    {i,f,g,o} of hidden unit r for 4 samples. Weights stored gate-interleaved
//    (Wint[k][r*4+g]) so the inner loop is 2x LDS.128 + 8x fma.rn.f32x2 per k.
//  - Cell state c lives in registers; gate buffer + cell_update pass removed.
//  - h double-buffered in SMEM -> only 2 __syncthreads per timestep.
//  - x for the whole block staged in SMEM once (no global traffic in loop).

#define TH      256
#define MM      16      // samples per block
#define HID     64
#define GATES   256
#define LL      168
#define HORIZON 24
#define SS      512
#define NBLOCKS 1024    // 16384 / MM
#define HS      20      // h row stride in floats (pad: conflict-free STS.128)
#define HBUF    (2 * HID * HS)   // one h buffer: 128 rows (h0 rows 0..63, h1 rows 64..127)

typedef unsigned long long u64t;

__device__ __forceinline__ u64t pk2(float a, float b) {
    u64t r;
    asm("mov.b64 %0, {%1, %2};" : "=l"(r) : "f"(a), "f"(b));
    return r;
}
__device__ __forceinline__ void upk2(u64t v, float& a, float& b) {
    asm("mov.b64 {%0, %1}, %2;" : "=f"(a), "=f"(b) : "l"(v));
}
__device__ __forceinline__ void fma2(u64t& d, u64t a, u64t b) {
    asm("fma.rn.f32x2 %0, %1, %2, %0;" : "+l"(d) : "l"(a), "l"(b));
}

__device__ __forceinline__ float sigf(float x) {
    return __fdividef(1.f, 1.f + __expf(-x));
}
__device__ __forceinline__ float tanhf_(float x) {
    return 1.f - __fdividef(2.f, __expf(2.f * x) + 1.f);
}

// acc[g][p] += Wint[k][r4+g] * h[k][ms + 2p .. 2p+1], k = 0..63
__device__ __forceinline__ void mat64(const float* __restrict__ Ws,
                                      const float* __restrict__ hb,
                                      int r4, int ms, u64t acc[4][2]) {
#pragma unroll 8
    for (int k = 0; k < HID; ++k) {
        float4 w = *(const float4*)(Ws + k * GATES + r4);
        float4 h = *(const float4*)(hb + k * HS + ms);
        u64t hA = pk2(h.x, h.y), hB = pk2(h.z, h.w);
        u64t w2;
        w2 = pk2(w.x, w.x); fma2(acc[0][0], hA, w2); fma2(acc[0][1], hB, w2);
        w2 = pk2(w.y, w.y); fma2(acc[1][0], hA, w2); fma2(acc[1][1], hB, w2);
        w2 = pk2(w.z, w.z); fma2(acc[2][0], hA, w2); fma2(acc[2][1], hB, w2);
        w2 = pk2(w.w, w.w); fma2(acc[3][0], hA, w2); fma2(acc[3][1], hB, w2);
    }
}

// In-register LSTM cell: c[4] updated, h (4 floats) stored as one STS.128.
__device__ __forceinline__ void cellstore(u64t acc[4][2], float c[4],
                                          float* __restrict__ dst) {
    float hv[4];
#pragma unroll
    for (int p = 0; p < 2; ++p) {
        float i0, i1, f0, f1, g0, g1, o0, o1;
        upk2(acc[0][p], i0, i1);
        upk2(acc[1][p], f0, f1);
        upk2(acc[2][p], g0, g1);
        upk2(acc[3][p], o0, o1);
        float nc0 = sigf(f0) * c[2 * p]     + sigf(i0) * tanhf_(g0);
        float nc1 = sigf(f1) * c[2 * p + 1] + sigf(i1) * tanhf_(g1);
        c[2 * p]     = nc0;
        c[2 * p + 1] = nc1;
        hv[2 * p]     = sigf(o0) * tanhf_(nc0);
        hv[2 * p + 1] = sigf(o1) * tanhf_(nc1);
    }
    *(float4*)dst = make_float4(hv[0], hv[1], hv[2], hv[3]);
}

__global__ void __launch_bounds__(TH, 1)
sitewise_lstm_kernel(const float* __restrict__ X,
                     const float* __restrict__ Wih0, const float* __restrict__ Whh0,
                     const float* __restrict__ bih0, const float* __restrict__ bhh0,
                     const float* __restrict__ Wih1, const float* __restrict__ Whh1,
                     const float* __restrict__ bih1, const float* __restrict__ bhh1,
                     const float* __restrict__ Wcih, const float* __restrict__ Wchh,
                     const float* __restrict__ bcih, const float* __restrict__ bchh,
                     const float* __restrict__ Wout, const float* __restrict__ bout,
                     float* __restrict__ out) {
    extern __shared__ float sm[];
    float* W0s  = sm;                         // 64  * 256  (Whh0; later Wchh)
    float* W1s  = W0s + HID * GATES;          // 128 * 256  ([Wih1;Whh1])
    float* hbuf = W1s + 2 * HID * GATES;      // 2 * 128 * HS (double-buffered h)
    float* xall = hbuf + 2 * HBUF;            // 168 * 16
    float* xcur = xall + LL * MM;             // 16
    float* wouts = xcur + MM;                 // 64

    const int tid = threadIdx.x;
    const int r   = tid & 63;       // hidden unit
    const int mg  = tid >> 6;       // sample group (0..3)
    const int ms  = mg * 4;
    const int r4  = r * 4;

    const int n0   = blockIdx.x * MM;
    const int xoff = (n0 >> 9) * (LL * SS) + (n0 & (SS - 1));

    // ---- stage weights (gate-interleaved, k-major) ----
    for (int idx = tid; idx < GATES * HID; idx += TH) {
        int jj = idx >> 6, k = idx & 63;         // matrix row jj, col k
        int g = jj >> 6, u = jj & 63;            // gate, unit
        int d = k * GATES + u * 4 + g;
        W0s[d] = Whh0[idx];
        W1s[d] = Wih1[idx];
        W1s[(HID + k) * GATES + u * 4 + g] = Whh1[idx];
    }
    // ---- stage x for this block's 16 samples, all 168 steps ----
    for (int idx = tid; idx < LL * MM; idx += TH) {
        int t = idx >> 4, s = idx & 15;
        xall[idx] = X[xoff + t * SS + s];
    }
    for (int idx = tid; idx < 2 * HBUF; idx += TH) hbuf[idx] = 0.f;
    if (tid < HID) wouts[tid] = Wout[tid];

    // per-thread constants: 4 gate rows {g*64 + r}
    float w0g[4], b0g[4], b1g[4];
#pragma unroll
    for (int g = 0; g < 4; ++g) {
        int row = g * 64 + r;
        w0g[g] = Wih0[row];
        b0g[g] = bih0[row] + bhh0[row];
        b1g[g] = bih1[row] + bhh1[row];
    }
    float c0[4] = {0.f, 0.f, 0.f, 0.f};
    float c1[4] = {0.f, 0.f, 0.f, 0.f};

    __syncthreads();

    // ================= encoder =================
    for (int t = 0; t < LL; ++t) {
        const int rd = (t & 1) * HBUF;
        const int wr = HBUF - rd;
        u64t acc[4][2];

        // ---- layer 0: g = x*wih0 + b + h0_{t-1} @ Whh0^T ----
        float4 xv = *(const float4*)(xall + t * MM + ms);
#pragma unroll
        for (int g = 0; g < 4; ++g) {
            acc[g][0] = pk2(fmaf(xv.x, w0g[g], b0g[g]), fmaf(xv.y, w0g[g], b0g[g]));
            acc[g][1] = pk2(fmaf(xv.z, w0g[g], b0g[g]), fmaf(xv.w, w0g[g], b0g[g]));
        }
        mat64(W0s, hbuf + rd, r4, ms, acc);                 // h0_{t-1}: rows 0..63 of rd
        cellstore(acc, c0, hbuf + wr + r * HS + ms);        // h0_t -> rows 0..63 of wr
        __syncthreads();

        // ---- layer 1: g = [h0_t; h1_{t-1}] @ [Wih1;Whh1]^T + b ----
#pragma unroll
        for (int g = 0; g < 4; ++g) {
            acc[g][0] = pk2(b1g[g], b1g[g]);
            acc[g][1] = pk2(b1g[g], b1g[g]);
        }
        mat64(W1s, hbuf + wr, r4, ms, acc);                 // h0_t (rows 0..63, wr)
        mat64(W1s + HID * GATES, hbuf + rd + HID * HS, r4, ms, acc); // h1_{t-1} (rows 64.., rd)
        cellstore(acc, c1, hbuf + wr + (HID + r) * HS + ms);// h1_t -> rows 64..127 of wr
        __syncthreads();
    }

    // ================= decoder =================
    // final state (t=167): wr was HBUF - (167&1)*HBUF = 0 -> h1 in buffer 0.
    for (int idx = tid; idx < GATES * HID; idx += TH) {
        int jj = idx >> 6, k = idx & 63;
        int g = jj >> 6, u = jj & 63;
        W0s[k * GATES + u * 4 + g] = Wchh[idx];
    }
    float wcg[4], bcg[4];
#pragma unroll
    for (int g = 0; g < 4; ++g) {
        int row = g * 64 + r;
        wcg[g] = Wcih[row];
        bcg[g] = bcih[row] + bchh[row];
    }
    if (tid < MM) xcur[tid] = xall[(LL - 1) * MM + tid];    // x_cur = x[:, L-1]
    const float bo = bout[0];
    __syncthreads();

    for (int d = 0; d < HORIZON; ++d) {
        const int rd = (d & 1) * HBUF;
        const int wr = HBUF - rd;
        u64t acc[4][2];

        float4 xv = *(const float4*)(xcur + ms);
#pragma unroll
        for (int g = 0; g < 4; ++g) {
            acc[g][0] = pk2(fmaf(xv.x, wcg[g], bcg[g]), fmaf(xv.y, wcg[g], bcg[g]));
            acc[g][1] = pk2(fmaf(xv.z, wcg[g], bcg[g]), fmaf(xv.w, wcg[g], bcg[g]));
        }
        mat64(W0s, hbuf + rd + HID * HS, r4, ms, acc);      // h1_{d-1}: rows 64..127 of rd
        cellstore(acc, c1, hbuf + wr + (HID + r) * HS + ms);
        __syncthreads();

        // output head: y = h1 @ Wout^T + b_out ; feeds back as next x
        if (tid < MM) {
            float y = bo;
#pragma unroll 8
            for (int k = 0; k < HID; ++k)
                y = fmaf(wouts[k], hbuf[wr + (HID + k) * HS + tid], y);
            int b = n0 >> 9, s = (n0 & (SS - 1)) + tid;
            out[(b * HORIZON + d) * SS + s] = y;
            xcur[tid] = y;
        }
        __syncthreads();
    }
}

extern "C" void kernel_launch(void* const* d_in, const int* in_sizes, int n_in,
                              void* d_out, int out_size) {
    const float* X    = (const float*)d_in[0];
    const float* Wih0 = (const float*)d_in[1];
    const float* Whh0 = (const float*)d_in[2];
    const float* bih0 = (const float*)d_in[3];
    const float* bhh0 = (const float*)d_in[4];
    const float* Wih1 = (const float*)d_in[5];
    const float* Whh1 = (const float*)d_in[6];
    const float* bih1 = (const float*)d_in[7];
    const float* bhh1 = (const float*)d_in[8];
    const float* Wcih = (const float*)d_in[9];
    const float* Wchh = (const float*)d_in[10];
    const float* bcih = (const float*)d_in[11];
    const float* bchh = (const float*)d_in[12];
    const float* Wout = (const float*)d_in[13];
    const float* bout = (const float*)d_in[14];

    const int smem_floats = HID * GATES          // W0s
                          + 2 * HID * GATES      // W1s
                          + 2 * HBUF             // hbuf (double-buffered)
                          + LL * MM              // xall
                          + MM                   // xcur
                          + HID;                 // wouts
    const int smem_bytes = smem_floats * (int)sizeof(float);

    cudaFuncSetAttribute(sitewise_lstm_kernel,
                         cudaFuncAttributeMaxDynamicSharedMemorySize, smem_bytes);

    sitewise_lstm_kernel<<<NBLOCKS, TH, smem_bytes>>>(
        X, Wih0, Whh0, bih0, bhh0, Wih1, Whh1, bih1, bhh1,
        Wcih, Wchh, bcih, bchh, Wout, bout, (float*)d_out);
}

// round 3
// speedup vs baseline: 1.4945x; 1.0127x over previous
#include <cuda_runtime.h>

// SiteWiseLSTM on GB300 (sm_103a) — round 3
// Identical structure to round 2; ONLY change is the lane mapping inside the
// block: mg = tid&3, r = tid>>2 (was r = tid&63, mg = tid>>6).
// Effect: within a warp the weight LDS.128 union is 8 distinct 16B lines
// (128B -> 1 wavefront, was 4) and the h LDS.128 union is 4 lines (64B -> 1
// wavefront). LDS per SM per k-iter drops 40 -> 16 cycles; kernel becomes
// FMA-bound.

#define TH      256
#define MM      16      // samples per block
#define HID     64
#define GATES   256
#define LL      168
#define HORIZON 24
#define SS      512
#define NBLOCKS 1024    // 16384 / MM
#define HS      20      // h row stride in floats
#define HBUF    (2 * HID * HS)

typedef unsigned long long u64t;

__device__ __forceinline__ u64t pk2(float a, float b) {
    u64t r;
    asm("mov.b64 %0, {%1, %2};" : "=l"(r) : "f"(a), "f"(b));
    return r;
}
__device__ __forceinline__ void upk2(u64t v, float& a, float& b) {
    asm("mov.b64 {%0, %1}, %2;" : "=f"(a), "=f"(b) : "l"(v));
}
__device__ __forceinline__ void fma2(u64t& d, u64t a, u64t b) {
    asm("fma.rn.f32x2 %0, %1, %2, %0;" : "+l"(d) : "l"(a), "l"(b));
}

__device__ __forceinline__ float sigf(float x) {
    return __fdividef(1.f, 1.f + __expf(-x));
}
__device__ __forceinline__ float tanhf_(float x) {
    return 1.f - __fdividef(2.f, __expf(2.f * x) + 1.f);
}

// acc[g][p] += Wint[k][r4+g] * h[k][ms + 2p .. 2p+1], k = 0..63
__device__ __forceinline__ void mat64(const float* __restrict__ Ws,
                                      const float* __restrict__ hb,
                                      int r4, int ms, u64t acc[4][2]) {
#pragma unroll 8
    for (int k = 0; k < HID; ++k) {
        float4 w = *(const float4*)(Ws + k * GATES + r4);
        float4 h = *(const float4*)(hb + k * HS + ms);
        u64t hA = pk2(h.x, h.y), hB = pk2(h.z, h.w);
        u64t w2;
        w2 = pk2(w.x, w.x); fma2(acc[0][0], hA, w2); fma2(acc[0][1], hB, w2);
        w2 = pk2(w.y, w.y); fma2(acc[1][0], hA, w2); fma2(acc[1][1], hB, w2);
        w2 = pk2(w.z, w.z); fma2(acc[2][0], hA, w2); fma2(acc[2][1], hB, w2);
        w2 = pk2(w.w, w.w); fma2(acc[3][0], hA, w2); fma2(acc[3][1], hB, w2);
    }
}

// In-register LSTM cell: c[4] updated, h (4 floats) stored as one STS.128.
__device__ __forceinline__ void cellstore(u64t acc[4][2], float c[4],
                                          float* __restrict__ dst) {
    float hv[4];
#pragma unroll
    for (int p = 0; p < 2; ++p) {
        float i0, i1, f0, f1, g0, g1, o0, o1;
        upk2(acc[0][p], i0, i1);
        upk2(acc[1][p], f0, f1);
        upk2(acc[2][p], g0, g1);
        upk2(acc[3][p], o0, o1);
        float nc0 = sigf(f0) * c[2 * p]     + sigf(i0) * tanhf_(g0);
        float nc1 = sigf(f1) * c[2 * p + 1] + sigf(i1) * tanhf_(g1);
        c[2 * p]     = nc0;
        c[2 * p + 1] = nc1;
        hv[2 * p]     = sigf(o0) * tanhf_(nc0);
        hv[2 * p + 1] = sigf(o1) * tanhf_(nc1);
    }
    *(float4*)dst = make_float4(hv[0], hv[1], hv[2], hv[3]);
}

__global__ void __launch_bounds__(TH, 1)
sitewise_lstm_kernel(const float* __restrict__ X,
                     const float* __restrict__ Wih0, const float* __restrict__ Whh0,
                     const float* __restrict__ bih0, const float* __restrict__ bhh0,
                     const float* __restrict__ Wih1, const float* __restrict__ Whh1,
                     const float* __restrict__ bih1, const float* __restrict__ bhh1,
                     const float* __restrict__ Wcih, const float* __restrict__ Wchh,
                     const float* __restrict__ bcih, const float* __restrict__ bchh,
                     const float* __restrict__ Wout, const float* __restrict__ bout,
                     float* __restrict__ out) {
    extern __shared__ float sm[];
    float* W0s  = sm;                         // 64  * 256  (Whh0; later Wchh)
    float* W1s  = W0s + HID * GATES;          // 128 * 256  ([Wih1;Whh1])
    float* hbuf = W1s + 2 * HID * GATES;      // 2 * 128 * HS (double-buffered h)
    float* xall = hbuf + 2 * HBUF;            // 168 * 16
    float* xcur = xall + LL * MM;             // 16
    float* wouts = xcur + MM;                 // 64

    const int tid = threadIdx.x;
    // Lane remap (the round-3 change): 4 consecutive lanes share a unit r and
    // cover the 4 sample groups. Warp = 8 units x 4 groups -> weight LDS.128
    // unions to 128B (1 wavefront), h LDS.128 unions to 64B (1 wavefront).
    const int mg  = tid & 3;        // sample group (0..3)
    const int r   = tid >> 2;       // hidden unit (0..63)
    const int ms  = mg * 4;
    const int r4  = r * 4;

    const int n0   = blockIdx.x * MM;
    const int xoff = (n0 >> 9) * (LL * SS) + (n0 & (SS - 1));

    // ---- stage weights (gate-interleaved, k-major) ----
    for (int idx = tid; idx < GATES * HID; idx += TH) {
        int jj = idx >> 6, k = idx & 63;         // matrix row jj, col k
        int g = jj >> 6, u = jj & 63;            // gate, unit
        int d = k * GATES + u * 4 + g;
        W0s[d] = Whh0[idx];
        W1s[d] = Wih1[idx];
        W1s[(HID + k) * GATES + u * 4 + g] = Whh1[idx];
    }
    // ---- stage x for this block's 16 samples, all 168 steps ----
    for (int idx = tid; idx < LL * MM; idx += TH) {
        int t = idx >> 4, s = idx & 15;
        xall[idx] = X[xoff + t * SS + s];
    }
    for (int idx = tid; idx < 2 * HBUF; idx += TH) hbuf[idx] = 0.f;
    if (tid < HID) wouts[tid] = Wout[tid];

    // per-thread constants: 4 gate rows {g*64 + r}
    float w0g[4], b0g[4], b1g[4];
#pragma unroll
    for (int g = 0; g < 4; ++g) {
        int row = g * 64 + r;
        w0g[g] = Wih0[row];
        b0g[g] = bih0[row] + bhh0[row];
        b1g[g] = bih1[row] + bhh1[row];
    }
    float c0[4] = {0.f, 0.f, 0.f, 0.f};
    float c1[4] = {0.f, 0.f, 0.f, 0.f};

    __syncthreads();

    // ================= encoder =================
    for (int t = 0; t < LL; ++t) {
        const int rd = (t & 1) * HBUF;
        const int wr = HBUF - rd;
        u64t acc[4][2];

        // ---- layer 0: g = x*wih0 + b + h0_{t-1} @ Whh0^T ----
        float4 xv = *(const float4*)(xall + t * MM + ms);
#pragma unroll
        for (int g = 0; g < 4; ++g) {
            acc[g][0] = pk2(fmaf(xv.x, w0g[g], b0g[g]), fmaf(xv.y, w0g[g], b0g[g]));
            acc[g][1] = pk2(fmaf(xv.z, w0g[g], b0g[g]), fmaf(xv.w, w0g[g], b0g[g]));
        }
        mat64(W0s, hbuf + rd, r4, ms, acc);                 // h0_{t-1}: rows 0..63 of rd
        cellstore(acc, c0, hbuf + wr + r * HS + ms);        // h0_t -> rows 0..63 of wr
        __syncthreads();

        // ---- layer 1: g = [h0_t; h1_{t-1}] @ [Wih1;Whh1]^T + b ----
#pragma unroll
        for (int g = 0; g < 4; ++g) {
            acc[g][0] = pk2(b1g[g], b1g[g]);
            acc[g][1] = pk2(b1g[g], b1g[g]);
        }
        mat64(W1s, hbuf + wr, r4, ms, acc);                 // h0_t (rows 0..63, wr)
        mat64(W1s + HID * GATES, hbuf + rd + HID * HS, r4, ms, acc); // h1_{t-1} (rows 64.., rd)
        cellstore(acc, c1, hbuf + wr + (HID + r) * HS + ms);// h1_t -> rows 64..127 of wr
        __syncthreads();
    }

    // ================= decoder =================
    // final state (t=167): wr = 0 -> h1 in buffer 0.
    for (int idx = tid; idx < GATES * HID; idx += TH) {
        int jj = idx >> 6, k = idx & 63;
        int g = jj >> 6, u = jj & 63;
        W0s[k * GATES + u * 4 + g] = Wchh[idx];
    }
    float wcg[4], bcg[4];
#pragma unroll
    for (int g = 0; g < 4; ++g) {
        int row = g * 64 + r;
        wcg[g] = Wcih[row];
        bcg[g] = bcih[row] + bchh[row];
    }
    if (tid < MM) xcur[tid] = xall[(LL - 1) * MM + tid];    // x_cur = x[:, L-1]
    const float bo = bout[0];
    __syncthreads();

    for (int d = 0; d < HORIZON; ++d) {
        const int rd = (d & 1) * HBUF;
        const int wr = HBUF - rd;
        u64t acc[4][2];

        float4 xv = *(const float4*)(xcur + ms);
#pragma unroll
        for (int g = 0; g < 4; ++g) {
            acc[g][0] = pk2(fmaf(xv.x, wcg[g], bcg[g]), fmaf(xv.y, wcg[g], bcg[g]));
            acc[g][1] = pk2(fmaf(xv.z, wcg[g], bcg[g]), fmaf(xv.w, wcg[g], bcg[g]));
        }
        mat64(W0s, hbuf + rd + HID * HS, r4, ms, acc);      // h1_{d-1}: rows 64..127 of rd
        cellstore(acc, c1, hbuf + wr + (HID + r) * HS + ms);
        __syncthreads();

        // output head: y = h1 @ Wout^T + b_out ; feeds back as next x
        if (tid < MM) {
            float y = bo;
#pragma unroll 8
            for (int k = 0; k < HID; ++k)
                y = fmaf(wouts[k], hbuf[wr + (HID + k) * HS + tid], y);
            int b = n0 >> 9, s = (n0 & (SS - 1)) + tid;
            out[(b * HORIZON + d) * SS + s] = y;
            xcur[tid] = y;
        }
        __syncthreads();
    }
}

extern "C" void kernel_launch(void* const* d_in, const int* in_sizes, int n_in,
                              void* d_out, int out_size) {
    const float* X    = (const float*)d_in[0];
    const float* Wih0 = (const float*)d_in[1];
    const float* Whh0 = (const float*)d_in[2];
    const float* bih0 = (const float*)d_in[3];
    const float* bhh0 = (const float*)d_in[4];
    const float* Wih1 = (const float*)d_in[5];
    const float* Whh1 = (const float*)d_in[6];
    const float* bih1 = (const float*)d_in[7];
    const float* bhh1 = (const float*)d_in[8];
    const float* Wcih = (const float*)d_in[9];
    const float* Wchh = (const float*)d_in[10];
    const float* bcih = (const float*)d_in[11];
    const float* bchh = (const float*)d_in[12];
    const float* Wout = (const float*)d_in[13];
    const float* bout = (const float*)d_in[14];

    const int smem_floats = HID * GATES          // W0s
                          + 2 * HID * GATES      // W1s
                          + 2 * HBUF             // hbuf (double-buffered)
                          + LL * MM              // xall
                          + MM                   // xcur
                          + HID;                 // wouts
    const int smem_bytes = smem_floats * (int)sizeof(float);

    cudaFuncSetAttribute(sitewise_lstm_kernel,
                         cudaFuncAttributeMaxDynamicSharedMemorySize, smem_bytes);

    sitewise_lstm_kernel<<<NBLOCKS, TH, smem_bytes>>>(
        X, Wih0, Whh0, bih0, bhh0, Wih1, Whh1, bih1, bhh1,
        Wcih, Wchh, bcih, bchh, Wout, bout, (float*)d_out);
}

// round 4
// speedup vs baseline: 1.7036x; 1.1399x over previous
#include <cuda_runtime.h>

// SiteWiseLSTM on GB300 (sm_103a) — round 4
// New model: LDS.128 costs 4 crossbar-cycles/warp structurally (dedup doesn't
// help), so the only lever is arithmetic intensity = FMAs per byte loaded.
// Tile: 2 units x 4 gates x 8 samples per thread (64 acc) -> 1.0 FMA/byte.
// TH=256, M=64 samples/block, 256 blocks (2 waves on 148 SMs).
// Single h buffer (3 __syncthreads per encoder step), weights in SMEM.
// Thread's 8 samples are split {4mg..4mg+3} u {32+4mg..4mg+35} so every
// 8-lane LDS/STS phase covers a contiguous 128B (conflict-free).

#define TH      256
#define MM      64      // samples per block
#define HID     64
#define GATES   256
#define LL      168
#define HOR     24
#define SS      512
#define NB      256     // 16384 / MM
#define HS      68      // h row stride in floats (64 + 4 pad; 272B, 16B-mult)

typedef unsigned long long u64t;

__device__ __forceinline__ u64t pk2(float a, float b) {
    u64t r;
    asm("mov.b64 %0, {%1, %2};" : "=l"(r) : "f"(a), "f"(b));
    return r;
}
__device__ __forceinline__ void upk2(u64t v, float& a, float& b) {
    asm("mov.b64 {%0, %1}, %2;" : "=f"(a), "=f"(b) : "l"(v));
}
__device__ __forceinline__ void fma2(u64t& d, u64t a, u64t b) {
    asm("fma.rn.f32x2 %0, %1, %2, %0;" : "+l"(d) : "l"(a), "l"(b));
}
__device__ __forceinline__ float sigf(float x) {
    return __fdividef(1.f, 1.f + __expf(-x));
}
__device__ __forceinline__ float tanhf_(float x) {
    return 1.f - __fdividef(2.f, __expf(2.f * x) + 1.f);
}

// acc[u][g][p] += W[k][8up+4u+g] * h[k][samples], k = 0..63.
// Ws points at (W base + w8), hb1/hb2 at (h base + ms1/ms2).
__device__ __forceinline__ void matG(const float* __restrict__ Ws,
                                     const float* __restrict__ hb1,
                                     const float* __restrict__ hb2,
                                     u64t acc[2][4][4]) {
#pragma unroll 4
    for (int k = 0; k < HID; ++k) {
        float4 wA = *(const float4*)(Ws + k * GATES);      // unit0 gates ifgo
        float4 wB = *(const float4*)(Ws + k * GATES + 4);  // unit1 gates ifgo
        ulonglong2 hA = *(const ulonglong2*)(hb1 + k * HS); // samples ms1..+3
        ulonglong2 hB = *(const ulonglong2*)(hb2 + k * HS); // samples ms2..+3
        u64t w2;
        w2 = pk2(wA.x, wA.x);
        fma2(acc[0][0][0], hA.x, w2); fma2(acc[0][0][1], hA.y, w2);
        fma2(acc[0][0][2], hB.x, w2); fma2(acc[0][0][3], hB.y, w2);
        w2 = pk2(wA.y, wA.y);
        fma2(acc[0][1][0], hA.x, w2); fma2(acc[0][1][1], hA.y, w2);
        fma2(acc[0][1][2], hB.x, w2); fma2(acc[0][1][3], hB.y, w2);
        w2 = pk2(wA.z, wA.z);
        fma2(acc[0][2][0], hA.x, w2); fma2(acc[0][2][1], hA.y, w2);
        fma2(acc[0][2][2], hB.x, w2); fma2(acc[0][2][3], hB.y, w2);
        w2 = pk2(wA.w, wA.w);
        fma2(acc[0][3][0], hA.x, w2); fma2(acc[0][3][1], hA.y, w2);
        fma2(acc[0][3][2], hB.x, w2); fma2(acc[0][3][3], hB.y, w2);
        w2 = pk2(wB.x, wB.x);
        fma2(acc[1][0][0], hA.x, w2); fma2(acc[1][0][1], hA.y, w2);
        fma2(acc[1][0][2], hB.x, w2); fma2(acc[1][0][3], hB.y, w2);
        w2 = pk2(wB.y, wB.y);
        fma2(acc[1][1][0], hA.x, w2); fma2(acc[1][1][1], hA.y, w2);
        fma2(acc[1][1][2], hB.x, w2); fma2(acc[1][1][3], hB.y, w2);
        w2 = pk2(wB.z, wB.z);
        fma2(acc[1][2][0], hA.x, w2); fma2(acc[1][2][1], hA.y, w2);
        fma2(acc[1][2][2], hB.x, w2); fma2(acc[1][2][3], hB.y, w2);
        w2 = pk2(wB.w, wB.w);
        fma2(acc[1][3][0], hA.x, w2); fma2(acc[1][3][1], hA.y, w2);
        fma2(acc[1][3][2], hB.x, w2); fma2(acc[1][3][3], hB.y, w2);
    }
}

// acc[u][g][0..1] += x(ms1 4 samples)*wg[u][g] ; acc[u][g][2..3] += x(ms2)
__device__ __forceinline__ void addx(u64t acc[2][4][4], float4 xA, float4 xB,
                                     const float wg[2][4]) {
    u64t xp0 = pk2(xA.x, xA.y), xp1 = pk2(xA.z, xA.w);
    u64t xp2 = pk2(xB.x, xB.y), xp3 = pk2(xB.z, xB.w);
#pragma unroll
    for (int u = 0; u < 2; ++u)
#pragma unroll
        for (int g = 0; g < 4; ++g) {
            u64t w2 = pk2(wg[u][g], wg[u][g]);
            fma2(acc[u][g][0], xp0, w2); fma2(acc[u][g][1], xp1, w2);
            fma2(acc[u][g][2], xp2, w2); fma2(acc[u][g][3], xp3, w2);
        }
}

// In-register LSTM cell for 2 units x 8 samples; writes h rows (u) at ms1/ms2.
// rowp = hbuf + (row0 + 2*up)*HS ; stores rowp[u*HS + ms1 + i], etc.
__device__ __forceinline__ void cellstore2(u64t acc[2][4][4], float* c,
                                           float* __restrict__ rowp,
                                           int ms1, int ms2) {
#pragma unroll
    for (int u = 0; u < 2; ++u) {
        float hv[8];
#pragma unroll
        for (int p = 0; p < 4; ++p) {
            float i0, i1, f0, f1, g0, g1, o0, o1;
            upk2(acc[u][0][p], i0, i1);
            upk2(acc[u][1][p], f0, f1);
            upk2(acc[u][2][p], g0, g1);
            upk2(acc[u][3][p], o0, o1);
            int ci = u * 8 + p * 2;
            float nc0 = sigf(f0) * c[ci]     + sigf(i0) * tanhf_(g0);
            float nc1 = sigf(f1) * c[ci + 1] + sigf(i1) * tanhf_(g1);
            c[ci] = nc0; c[ci + 1] = nc1;
            hv[p * 2]     = sigf(o0) * tanhf_(nc0);
            hv[p * 2 + 1] = sigf(o1) * tanhf_(nc1);
        }
        *(float4*)(rowp + u * HS + ms1) = make_float4(hv[0], hv[1], hv[2], hv[3]);
        *(float4*)(rowp + u * HS + ms2) = make_float4(hv[4], hv[5], hv[6], hv[7]);
    }
}

__global__ void __launch_bounds__(TH, 1)
sitewise_lstm_kernel(const float* __restrict__ X,
                     const float* __restrict__ Wih0, const float* __restrict__ Whh0,
                     const float* __restrict__ bih0, const float* __restrict__ bhh0,
                     const float* __restrict__ Wih1, const float* __restrict__ Whh1,
                     const float* __restrict__ bih1, const float* __restrict__ bhh1,
                     const float* __restrict__ Wcih, const float* __restrict__ Wchh,
                     const float* __restrict__ bcih, const float* __restrict__ bchh,
                     const float* __restrict__ Wout, const float* __restrict__ bout,
                     float* __restrict__ out) {
    extern __shared__ float sm[];
    float* W0s  = sm;                      // 64 k  x 256  (Whh0; later Wchh)
    float* W1s  = W0s + HID * GATES;       // 128 k x 256  ([Wih1;Whh1])
    float* hbuf = W1s + 2 * HID * GATES;   // 128 rows x HS (rows 0-63 h0, 64-127 h1)
    float* xcur = hbuf + 2 * HID * HS;     // 64
    float* wouts = xcur + MM;              // 64

    const int tid = threadIdx.x;
    const int mg  = tid & 7;               // sample group
    const int up  = tid >> 3;              // unit pair (units 2up, 2up+1)
    const int ms1 = mg * 4;                // first 4 samples
    const int ms2 = 32 + mg * 4;           // second 4 samples
    const int w8  = up * 8;

    const int n0 = blockIdx.x * MM;
    const int b  = n0 >> 9;
    const int s0 = n0 & (SS - 1);
    const long xrow = (long)b * LL * SS + s0;

    // ---- stage weights (gate-interleaved, k-major): Wint[k][u*4+g] ----
    for (int idx = tid; idx < GATES * HID; idx += TH) {
        int jj = idx >> 6, k = idx & 63;   // matrix row jj, col k
        int g = jj >> 6, u = jj & 63;
        int d = k * GATES + u * 4 + g;
        W0s[d] = Whh0[idx];
        W1s[d] = Wih1[idx];
        W1s[(HID + k) * GATES + u * 4 + g] = Whh1[idx];
    }
    for (int idx = tid; idx < 2 * HID * HS; idx += TH) hbuf[idx] = 0.f;
    if (tid < HID) wouts[tid] = Wout[tid];

    // per-thread gate constants: rows g*64 + (2up+u)
    float w0g[2][4], b0g[2][4], b1g[2][4];
#pragma unroll
    for (int u = 0; u < 2; ++u)
#pragma unroll
        for (int g = 0; g < 4; ++g) {
            int row = g * 64 + 2 * up + u;
            w0g[u][g] = Wih0[row];
            b0g[u][g] = bih0[row] + bhh0[row];
            b1g[u][g] = bih1[row] + bhh1[row];
        }
    float c0[16], c1[16];
#pragma unroll
    for (int i = 0; i < 16; ++i) { c0[i] = 0.f; c1[i] = 0.f; }

    float* rowp0 = hbuf + (2 * up) * HS;            // this thread's h0 rows
    float* rowp1 = hbuf + (HID + 2 * up) * HS;      // this thread's h1 rows

    __syncthreads();

    // ================= encoder =================
    for (int t = 0; t < LL; ++t) {
        // prefetch x for this step (completes under the matmul)
        float4 xA = __ldg((const float4*)(X + xrow + (long)t * SS + ms1));
        float4 xB = __ldg((const float4*)(X + xrow + (long)t * SS + ms2));

        u64t acc[2][4][4];
        // ---- layer 0: acc = b0 ; += Whh0 . h0_old ; += x*wih0 ----
#pragma unroll
        for (int u = 0; u < 2; ++u)
#pragma unroll
            for (int g = 0; g < 4; ++g) {
                u64t bb = pk2(b0g[u][g], b0g[u][g]);
                acc[u][g][0] = bb; acc[u][g][1] = bb;
                acc[u][g][2] = bb; acc[u][g][3] = bb;
            }
        matG(W0s + w8, hbuf + ms1, hbuf + ms2, acc);
        addx(acc, xA, xB, w0g);
        __syncthreads();                                 // h0_old reads done
        cellstore2(acc, c0, rowp0, ms1, ms2);            // write h0_new
        __syncthreads();                                 // h0_new visible

        // ---- layer 1: acc = b1 ; += Wih1 . h0_new ; += Whh1 . h1_old ----
#pragma unroll
        for (int u = 0; u < 2; ++u)
#pragma unroll
            for (int g = 0; g < 4; ++g) {
                u64t bb = pk2(b1g[u][g], b1g[u][g]);
                acc[u][g][0] = bb; acc[u][g][1] = bb;
                acc[u][g][2] = bb; acc[u][g][3] = bb;
            }
        matG(W1s + w8, hbuf + ms1, hbuf + ms2, acc);                       // h0_new
        matG(W1s + HID * GATES + w8, hbuf + HID * HS + ms1,
             hbuf + HID * HS + ms2, acc);                                  // h1_old
        __syncthreads();                                 // h1_old reads done
        cellstore2(acc, c1, rowp1, ms1, ms2);            // write h1_new
        // no 4th barrier: next step only reads h1 after its 2nd barrier
    }

    // ================= decoder =================
    __syncthreads();                                     // h1_new visible
    for (int idx = tid; idx < GATES * HID; idx += TH) {  // W0s <- Wchh
        int jj = idx >> 6, k = idx & 63;
        int g = jj >> 6, u = jj & 63;
        W0s[k * GATES + u * 4 + g] = Wchh[idx];
    }
    float wcg[2][4], bcg[2][4];
#pragma unroll
    for (int u = 0; u < 2; ++u)
#pragma unroll
        for (int g = 0; g < 4; ++g) {
            int row = g * 64 + 2 * up + u;
            wcg[u][g] = Wcih[row];
            bcg[u][g] = bcih[row] + bchh[row];
        }
    if (tid < MM) xcur[tid] = X[xrow + (long)(LL - 1) * SS + tid];
    const float bo = bout[0];
    __syncthreads();

    for (int d = 0; d < HOR; ++d) {
        u64t acc[2][4][4];
#pragma unroll
        for (int u = 0; u < 2; ++u)
#pragma unroll
            for (int g = 0; g < 4; ++g) {
                u64t bb = pk2(bcg[u][g], bcg[u][g]);
                acc[u][g][0] = bb; acc[u][g][1] = bb;
                acc[u][g][2] = bb; acc[u][g][3] = bb;
            }
        float4 xA = *(const float4*)(xcur + ms1);
        float4 xB = *(const float4*)(xcur + ms2);
        matG(W0s + w8, hbuf + HID * HS + ms1, hbuf + HID * HS + ms2, acc); // h1_old
        addx(acc, xA, xB, wcg);
        __syncthreads();                                 // h1_old + xcur reads done
        cellstore2(acc, c1, rowp1, ms1, ms2);            // h1_new
        __syncthreads();                                 // h1_new visible

        // output head: y = h1 @ Wout^T + bo ; feeds back as next x
        if (tid < MM) {
            float y = bo;
#pragma unroll 8
            for (int k = 0; k < HID; ++k)
                y = fmaf(wouts[k], hbuf[(HID + k) * HS + tid], y);
            out[((long)(b * HOR + d)) * SS + s0 + tid] = y;
            xcur[tid] = y;
        }
        __syncthreads();                                 // xcur visible
    }
}

extern "C" void kernel_launch(void* const* d_in, const int* in_sizes, int n_in,
                              void* d_out, int out_size) {
    const float* X    = (const float*)d_in[0];
    const float* Wih0 = (const float*)d_in[1];
    const float* Whh0 = (const float*)d_in[2];
    const float* bih0 = (const float*)d_in[3];
    const float* bhh0 = (const float*)d_in[4];
    const float* Wih1 = (const float*)d_in[5];
    const float* Whh1 = (const float*)d_in[6];
    const float* bih1 = (const float*)d_in[7];
    const float* bhh1 = (const float*)d_in[8];
    const float* Wcih = (const float*)d_in[9];
    const float* Wchh = (const float*)d_in[10];
    const float* bcih = (const float*)d_in[11];
    const float* bchh = (const float*)d_in[12];
    const float* Wout = (const float*)d_in[13];
    const float* bout = (const float*)d_in[14];

    const int smem_floats = HID * GATES          // W0s
                          + 2 * HID * GATES      // W1s
                          + 2 * HID * HS         // hbuf
                          + MM                   // xcur
                          + HID;                 // wouts
    const int smem_bytes = smem_floats * (int)sizeof(float);

    cudaFuncSetAttribute(sitewise_lstm_kernel,
                         cudaFuncAttributeMaxDynamicSharedMemorySize, smem_bytes);

    sitewise_lstm_kernel<<<NB, TH, smem_bytes>>>(
        X, Wih0, Whh0, bih0, bhh0, Wih1, Whh1, bih1, bhh1,
        Wcih, Wchh, bcih, bchh, Wout, bout, (float*)d_out);
}

// round 6
// speedup vs baseline: 1.7064x; 1.0017x over previous
#include <cuda_runtime.h>

// SiteWiseLSTM on GB300 (sm_103a) — round 5
// Same 2-unit x 4-gate x 8-sample register tile as round 4. Change: barrier
// restructure (3 -> 2 per encoder step) that places each MUFU epilogue burst
// in a barrier-free window adjacent to independent FMA work:
//   matG0(h0_old) | bar1 | cellstore0+STS(h0), matG1b(Whh1.h1_old) | bar2 |
//   matG1a(Wih1.h0_new), cellstore1+STS(h1) | loop
// All h0/h1 row sets are disjoint, so the writes in each window never race
// the reads in the same window; publication happens across bar1/bar2.

#define TH      256
#define MM      64      // samples per block
#define HID     64
#define GATES   256
#define LL      168
#define HOR     24
#define SS      512
#define NB      256     // 16384 / MM
#define HS      68      // h row stride in floats

typedef unsigned long long u64t;

__device__ __forceinline__ u64t pk2(float a, float b) {
    u64t r;
    asm("mov.b64 %0, {%1, %2};" : "=l"(r) : "f"(a), "f"(b));
    return r;
}
__device__ __forceinline__ void upk2(u64t v, float& a, float& b) {
    asm("mov.b64 {%0, %1}, %2;" : "=f"(a), "=f"(b) : "l"(v));
}
__device__ __forceinline__ void fma2(u64t& d, u64t a, u64t b) {
    asm("fma.rn.f32x2 %0, %1, %2, %0;" : "+l"(d) : "l"(a), "l"(b));
}
__device__ __forceinline__ float sigf(float x) {
    return __fdividef(1.f, 1.f + __expf(-x));
}
__device__ __forceinline__ float tanhf_(float x) {
    return 1.f - __fdividef(2.f, __expf(2.f * x) + 1.f);
}

// acc[u][g][p] += W[k][8up+4u+g] * h[k][samples], k = 0..63.
__device__ __forceinline__ void matG(const float* __restrict__ Ws,
                                     const float* __restrict__ hb1,
                                     const float* __restrict__ hb2,
                                     u64t acc[2][4][4]) {
#pragma unroll 4
    for (int k = 0; k < HID; ++k) {
        float4 wA = *(const float4*)(Ws + k * GATES);
        float4 wB = *(const float4*)(Ws + k * GATES + 4);
        ulonglong2 hA = *(const ulonglong2*)(hb1 + k * HS);
        ulonglong2 hB = *(const ulonglong2*)(hb2 + k * HS);
        u64t w2;
        w2 = pk2(wA.x, wA.x);
        fma2(acc[0][0][0], hA.x, w2); fma2(acc[0][0][1], hA.y, w2);
        fma2(acc[0][0][2], hB.x, w2); fma2(acc[0][0][3], hB.y, w2);
        w2 = pk2(wA.y, wA.y);
        fma2(acc[0][1][0], hA.x, w2); fma2(acc[0][1][1], hA.y, w2);
        fma2(acc[0][1][2], hB.x, w2); fma2(acc[0][1][3], hB.y, w2);
        w2 = pk2(wA.z, wA.z);
        fma2(acc[0][2][0], hA.x, w2); fma2(acc[0][2][1], hA.y, w2);
        fma2(acc[0][2][2], hB.x, w2); fma2(acc[0][2][3], hB.y, w2);
        w2 = pk2(wA.w, wA.w);
        fma2(acc[0][3][0], hA.x, w2); fma2(acc[0][3][1], hA.y, w2);
        fma2(acc[0][3][2], hB.x, w2); fma2(acc[0][3][3], hB.y, w2);
        w2 = pk2(wB.x, wB.x);
        fma2(acc[1][0][0], hA.x, w2); fma2(acc[1][0][1], hA.y, w2);
        fma2(acc[1][0][2], hB.x, w2); fma2(acc[1][0][3], hB.y, w2);
        w2 = pk2(wB.y, wB.y);
        fma2(acc[1][1][0], hA.x, w2); fma2(acc[1][1][1], hA.y, w2);
        fma2(acc[1][1][2], hB.x, w2); fma2(acc[1][1][3], hB.y, w2);
        w2 = pk2(wB.z, wB.z);
        fma2(acc[1][2][0], hA.x, w2); fma2(acc[1][2][1], hA.y, w2);
        fma2(acc[1][2][2], hB.x, w2); fma2(acc[1][2][3], hB.y, w2);
        w2 = pk2(wB.w, wB.w);
        fma2(acc[1][3][0], hA.x, w2); fma2(acc[1][3][1], hA.y, w2);
        fma2(acc[1][3][2], hB.x, w2); fma2(acc[1][3][3], hB.y, w2);
    }
}

__device__ __forceinline__ void addx(u64t acc[2][4][4], float4 xA, float4 xB,
                                     const float wg[2][4]) {
    u64t xp0 = pk2(xA.x, xA.y), xp1 = pk2(xA.z, xA.w);
    u64t xp2 = pk2(xB.x, xB.y), xp3 = pk2(xB.z, xB.w);
#pragma unroll
    for (int u = 0; u < 2; ++u)
#pragma unroll
        for (int g = 0; g < 4; ++g) {
            u64t w2 = pk2(wg[u][g], wg[u][g]);
            fma2(acc[u][g][0], xp0, w2); fma2(acc[u][g][1], xp1, w2);
            fma2(acc[u][g][2], xp2, w2); fma2(acc[u][g][3], xp3, w2);
        }
}

__device__ __forceinline__ void initacc(u64t acc[2][4][4], const float bg[2][4]) {
#pragma unroll
    for (int u = 0; u < 2; ++u)
#pragma unroll
        for (int g = 0; g < 4; ++g) {
            u64t bb = pk2(bg[u][g], bg[u][g]);
            acc[u][g][0] = bb; acc[u][g][1] = bb;
            acc[u][g][2] = bb; acc[u][g][3] = bb;
        }
}

// In-register LSTM cell for 2 units x 8 samples; writes h rows at ms1/ms2.
__device__ __forceinline__ void cellstore2(u64t acc[2][4][4], float* c,
                                           float* __restrict__ rowp,
                                           int ms1, int ms2) {
#pragma unroll
    for (int u = 0; u < 2; ++u) {
        float hv[8];
#pragma unroll
        for (int p = 0; p < 4; ++p) {
            float i0, i1, f0, f1, g0, g1, o0, o1;
            upk2(acc[u][0][p], i0, i1);
            upk2(acc[u][1][p], f0, f1);
            upk2(acc[u][2][p], g0, g1);
            upk2(acc[u][3][p], o0, o1);
            int ci = u * 8 + p * 2;
            float nc0 = sigf(f0) * c[ci]     + sigf(i0) * tanhf_(g0);
            float nc1 = sigf(f1) * c[ci + 1] + sigf(i1) * tanhf_(g1);
            c[ci] = nc0; c[ci + 1] = nc1;
            hv[p * 2]     = sigf(o0) * tanhf_(nc0);
            hv[p * 2 + 1] = sigf(o1) * tanhf_(nc1);
        }
        *(float4*)(rowp + u * HS + ms1) = make_float4(hv[0], hv[1], hv[2], hv[3]);
        *(float4*)(rowp + u * HS + ms2) = make_float4(hv[4], hv[5], hv[6], hv[7]);
    }
}

__global__ void __launch_bounds__(TH, 1)
sitewise_lstm_kernel(const float* __restrict__ X,
                     const float* __restrict__ Wih0, const float* __restrict__ Whh0,
                     const float* __restrict__ bih0, const float* __restrict__ bhh0,
                     const float* __restrict__ Wih1, const float* __restrict__ Whh1,
                     const float* __restrict__ bih1, const float* __restrict__ bhh1,
                     const float* __restrict__ Wcih, const float* __restrict__ Wchh,
                     const float* __restrict__ bcih, const float* __restrict__ bchh,
                     const float* __restrict__ Wout, const float* __restrict__ bout,
                     float* __restrict__ out) {
    extern __shared__ float sm[];
    float* W0s  = sm;                      // 64 k  x 256  (Whh0; later Wchh)
    float* W1s  = W0s + HID * GATES;       // 128 k x 256  ([Wih1;Whh1])
    float* hbuf = W1s + 2 * HID * GATES;   // 128 rows x HS (0-63 h0, 64-127 h1)
    float* xcur = hbuf + 2 * HID * HS;     // 64
    float* wouts = xcur + MM;              // 64

    const int tid = threadIdx.x;
    const int mg  = tid & 7;
    const int up  = tid >> 3;
    const int ms1 = mg * 4;
    const int ms2 = 32 + mg * 4;
    const int w8  = up * 8;

    const int n0 = blockIdx.x * MM;
    const int b  = n0 >> 9;
    const int s0 = n0 & (SS - 1);
    const long xrow = (long)b * LL * SS + s0;

    // ---- stage weights (gate-interleaved, k-major): Wint[k][u*4+g] ----
    for (int idx = tid; idx < GATES * HID; idx += TH) {
        int jj = idx >> 6, k = idx & 63;
        int g = jj >> 6, u = jj & 63;
        int d = k * GATES + u * 4 + g;
        W0s[d] = Whh0[idx];
        W1s[d] = Wih1[idx];
        W1s[(HID + k) * GATES + u * 4 + g] = Whh1[idx];
    }
    for (int idx = tid; idx < 2 * HID * HS; idx += TH) hbuf[idx] = 0.f;
    if (tid < HID) wouts[tid] = Wout[tid];

    float w0g[2][4], b0g[2][4], b1g[2][4];
#pragma unroll
    for (int u = 0; u < 2; ++u)
#pragma unroll
        for (int g = 0; g < 4; ++g) {
            int row = g * 64 + 2 * up + u;
            w0g[u][g] = Wih0[row];
            b0g[u][g] = bih0[row] + bhh0[row];
            b1g[u][g] = bih1[row] + bhh1[row];
        }
    float c0[16], c1[16];
#pragma unroll
    for (int i = 0; i < 16; ++i) { c0[i] = 0.f; c1[i] = 0.f; }

    float* rowp0 = hbuf + (2 * up) * HS;
    float* rowp1 = hbuf + (HID + 2 * up) * HS;

    __syncthreads();

    // ================= encoder (2 barriers per step) =================
    for (int t = 0; t < LL; ++t) {
        float4 xA = __ldg((const float4*)(X + xrow + (long)t * SS + ms1));
        float4 xB = __ldg((const float4*)(X + xrow + (long)t * SS + ms2));

        u64t acc[2][4][4];
        // ---- layer 0: b0 + Whh0.h0_old + x*wih0 ----
        initacc(acc, b0g);
        matG(W0s + w8, hbuf + ms1, hbuf + ms2, acc);        // reads h0_old
        addx(acc, xA, xB, w0g);
        __syncthreads();                                    // bar1: h0_old reads done

        // window A (barrier-free): MUFU epilogue of layer0 + FMA of matG1b.
        cellstore2(acc, c0, rowp0, ms1, ms2);               // writes h0_new (h0 rows)
        initacc(acc, b1g);
        matG(W1s + HID * GATES + w8, hbuf + HID * HS + ms1,
             hbuf + HID * HS + ms2, acc);                   // Whh1 . h1_old (h1 rows)
        __syncthreads();                                    // bar2: h0_new published,
                                                            //       h1_old reads done
        // window B (barrier-free): FMA of matG1a + MUFU epilogue of layer1.
        matG(W1s + w8, hbuf + ms1, hbuf + ms2, acc);        // Wih1 . h0_new (h0 rows)
        cellstore2(acc, c1, rowp1, ms1, ms2);               // writes h1_new (h1 rows)
        // publication of h1_new to next step happens across next bar1.
    }

    // ================= decoder =================
    __syncthreads();                                        // h1_new visible
    for (int idx = tid; idx < GATES * HID; idx += TH) {     // W0s <- Wchh
        int jj = idx >> 6, k = idx & 63;
        int g = jj >> 6, u = jj & 63;
        W0s[k * GATES + u * 4 + g] = Wchh[idx];
    }
    float wcg[2][4], bcg[2][4];
#pragma unroll
    for (int u = 0; u < 2; ++u)
#pragma unroll
        for (int g = 0; g < 4; ++g) {
            int row = g * 64 + 2 * up + u;
            wcg[u][g] = Wcih[row];
            bcg[u][g] = bcih[row] + bchh[row];
        }
    if (tid < MM) xcur[tid] = X[xrow + (long)(LL - 1) * SS + tid];
    const float bo = bout[0];
    __syncthreads();

    for (int d = 0; d < HOR; ++d) {
        u64t acc[2][4][4];
        initacc(acc, bcg);
        float4 xA = *(const float4*)(xcur + ms1);
        float4 xB = *(const float4*)(xcur + ms2);
        matG(W0s + w8, hbuf + HID * HS + ms1, hbuf + HID * HS + ms2, acc);
        addx(acc, xA, xB, wcg);
        __syncthreads();                                    // h1_old + xcur reads done
        cellstore2(acc, c1, rowp1, ms1, ms2);               // h1_new
        __syncthreads();                                    // h1_new visible

        if (tid < MM) {
            float y = bo;
#pragma unroll 8
            for (int k = 0; k < HID; ++k)
                y = fmaf(wouts[k], hbuf[(HID + k) * HS + tid], y);
            out[((long)(b * HOR + d)) * SS + s0 + tid] = y;
            xcur[tid] = y;
        }
        __syncthreads();                                    // xcur visible
    }
}

extern "C" void kernel_launch(void* const* d_in, const int* in_sizes, int n_in,
                              void* d_out, int out_size) {
    const float* X    = (const float*)d_in[0];
    const float* Wih0 = (const float*)d_in[1];
    const float* Whh0 = (const float*)d_in[2];
    const float* bih0 = (const float*)d_in[3];
    const float* bhh0 = (const float*)d_in[4];
    const float* Wih1 = (const float*)d_in[5];
    const float* Whh1 = (const float*)d_in[6];
    const float* bih1 = (const float*)d_in[7];
    const float* bhh1 = (const float*)d_in[8];
    const float* Wcih = (const float*)d_in[9];
    const float* Wchh = (const float*)d_in[10];
    const float* bcih = (const float*)d_in[11];
    const float* bchh = (const float*)d_in[12];
    const float* Wout = (const float*)d_in[13];
    const float* bout = (const float*)d_in[14];

    const int smem_floats = HID * GATES
                          + 2 * HID * GATES
                          + 2 * HID * HS
                          + MM
                          + HID;
    const int smem_bytes = smem_floats * (int)sizeof(float);

    cudaFuncSetAttribute(sitewise_lstm_kernel,
                         cudaFuncAttributeMaxDynamicSharedMemorySize, smem_bytes);

    sitewise_lstm_kernel<<<NB, TH, smem_bytes>>>(
        X, Wih0, Whh0, bih0, bhh0, Wih1, Whh1, bih1, bhh1,
        Wcih, Wchh, bcih, bchh, Wout, bout, (float*)d_out);
}

// round 7
// speedup vs baseline: 1.7826x; 1.0446x over previous
#include <cuda_runtime.h>

// SiteWiseLSTM on GB300 (sm_103a) — round 6
// Identical to round 5 except activations use the HW tanh unit:
//   tanh(x)    -> tanh.approx.f32            (1 instr, 1 MUFU; was 6 instr/2 MUFU)
//   sigmoid(x) -> 0.5*tanh(0.5x) + 0.5       (3 instr, 1 MUFU; was 4 instr/2 MUFU)
// Cuts ~420 issue-slots/warp/step and halves MUFU pipe pressure; shortens the
// epilogue dependency chain ~2x. abs err of tanh.approx ~1e-4, recurrence is
// contractive -> expected rel_err ~1e-4 (budget 1e-3).

#define TH      256
#define MM      64      // samples per block
#define HID     64
#define GATES   256
#define LL      168
#define HOR     24
#define SS      512
#define NB      256     // 16384 / MM
#define HS      68      // h row stride in floats

typedef unsigned long long u64t;

__device__ __forceinline__ u64t pk2(float a, float b) {
    u64t r;
    asm("mov.b64 %0, {%1, %2};" : "=l"(r) : "f"(a), "f"(b));
    return r;
}
__device__ __forceinline__ void upk2(u64t v, float& a, float& b) {
    asm("mov.b64 {%0, %1}, %2;" : "=f"(a), "=f"(b) : "l"(v));
}
__device__ __forceinline__ void fma2(u64t& d, u64t a, u64t b) {
    asm("fma.rn.f32x2 %0, %1, %2, %0;" : "+l"(d) : "l"(a), "l"(b));
}
__device__ __forceinline__ float tanha(float x) {
    float y;
    asm("tanh.approx.f32 %0, %1;" : "=f"(y) : "f"(x));
    return y;
}
__device__ __forceinline__ float sigf(float x) {
    return fmaf(0.5f, tanha(0.5f * x), 0.5f);
}

// acc[u][g][p] += W[k][8up+4u+g] * h[k][samples], k = 0..63.
__device__ __forceinline__ void matG(const float* __restrict__ Ws,
                                     const float* __restrict__ hb1,
                                     const float* __restrict__ hb2,
                                     u64t acc[2][4][4]) {
#pragma unroll 4
    for (int k = 0; k < HID; ++k) {
        float4 wA = *(const float4*)(Ws + k * GATES);
        float4 wB = *(const float4*)(Ws + k * GATES + 4);
        ulonglong2 hA = *(const ulonglong2*)(hb1 + k * HS);
        ulonglong2 hB = *(const ulonglong2*)(hb2 + k * HS);
        u64t w2;
        w2 = pk2(wA.x, wA.x);
        fma2(acc[0][0][0], hA.x, w2); fma2(acc[0][0][1], hA.y, w2);
        fma2(acc[0][0][2], hB.x, w2); fma2(acc[0][0][3], hB.y, w2);
        w2 = pk2(wA.y, wA.y);
        fma2(acc[0][1][0], hA.x, w2); fma2(acc[0][1][1], hA.y, w2);
        fma2(acc[0][1][2], hB.x, w2); fma2(acc[0][1][3], hB.y, w2);
        w2 = pk2(wA.z, wA.z);
        fma2(acc[0][2][0], hA.x, w2); fma2(acc[0][2][1], hA.y, w2);
        fma2(acc[0][2][2], hB.x, w2); fma2(acc[0][2][3], hB.y, w2);
        w2 = pk2(wA.w, wA.w);
        fma2(acc[0][3][0], hA.x, w2); fma2(acc[0][3][1], hA.y, w2);
        fma2(acc[0][3][2], hB.x, w2); fma2(acc[0][3][3], hB.y, w2);
        w2 = pk2(wB.x, wB.x);
        fma2(acc[1][0][0], hA.x, w2); fma2(acc[1][0][1], hA.y, w2);
        fma2(acc[1][0][2], hB.x, w2); fma2(acc[1][0][3], hB.y, w2);
        w2 = pk2(wB.y, wB.y);
        fma2(acc[1][1][0], hA.x, w2); fma2(acc[1][1][1], hA.y, w2);
        fma2(acc[1][1][2], hB.x, w2); fma2(acc[1][1][3], hB.y, w2);
        w2 = pk2(wB.z, wB.z);
        fma2(acc[1][2][0], hA.x, w2); fma2(acc[1][2][1], hA.y, w2);
        fma2(acc[1][2][2], hB.x, w2); fma2(acc[1][2][3], hB.y, w2);
        w2 = pk2(wB.w, wB.w);
        fma2(acc[1][3][0], hA.x, w2); fma2(acc[1][3][1], hA.y, w2);
        fma2(acc[1][3][2], hB.x, w2); fma2(acc[1][3][3], hB.y, w2);
    }
}

__device__ __forceinline__ void addx(u64t acc[2][4][4], float4 xA, float4 xB,
                                     const float wg[2][4]) {
    u64t xp0 = pk2(xA.x, xA.y), xp1 = pk2(xA.z, xA.w);
    u64t xp2 = pk2(xB.x, xB.y), xp3 = pk2(xB.z, xB.w);
#pragma unroll
    for (int u = 0; u < 2; ++u)
#pragma unroll
        for (int g = 0; g < 4; ++g) {
            u64t w2 = pk2(wg[u][g], wg[u][g]);
            fma2(acc[u][g][0], xp0, w2); fma2(acc[u][g][1], xp1, w2);
            fma2(acc[u][g][2], xp2, w2); fma2(acc[u][g][3], xp3, w2);
        }
}

__device__ __forceinline__ void initacc(u64t acc[2][4][4], const float bg[2][4]) {
#pragma unroll
    for (int u = 0; u < 2; ++u)
#pragma unroll
        for (int g = 0; g < 4; ++g) {
            u64t bb = pk2(bg[u][g], bg[u][g]);
            acc[u][g][0] = bb; acc[u][g][1] = bb;
            acc[u][g][2] = bb; acc[u][g][3] = bb;
        }
}

// In-register LSTM cell for 2 units x 8 samples; writes h rows at ms1/ms2.
__device__ __forceinline__ void cellstore2(u64t acc[2][4][4], float* c,
                                           float* __restrict__ rowp,
                                           int ms1, int ms2) {
#pragma unroll
    for (int u = 0; u < 2; ++u) {
        float hv[8];
#pragma unroll
        for (int p = 0; p < 4; ++p) {
            float i0, i1, f0, f1, g0, g1, o0, o1;
            upk2(acc[u][0][p], i0, i1);
            upk2(acc[u][1][p], f0, f1);
            upk2(acc[u][2][p], g0, g1);
            upk2(acc[u][3][p], o0, o1);
            int ci = u * 8 + p * 2;
            float nc0 = sigf(f0) * c[ci]     + sigf(i0) * tanha(g0);
            float nc1 = sigf(f1) * c[ci + 1] + sigf(i1) * tanha(g1);
            c[ci] = nc0; c[ci + 1] = nc1;
            hv[p * 2]     = sigf(o0) * tanha(nc0);
            hv[p * 2 + 1] = sigf(o1) * tanha(nc1);
        }
        *(float4*)(rowp + u * HS + ms1) = make_float4(hv[0], hv[1], hv[2], hv[3]);
        *(float4*)(rowp + u * HS + ms2) = make_float4(hv[4], hv[5], hv[6], hv[7]);
    }
}

__global__ void __launch_bounds__(TH, 1)
sitewise_lstm_kernel(const float* __restrict__ X,
                     const float* __restrict__ Wih0, const float* __restrict__ Whh0,
                     const float* __restrict__ bih0, const float* __restrict__ bhh0,
                     const float* __restrict__ Wih1, const float* __restrict__ Whh1,
                     const float* __restrict__ bih1, const float* __restrict__ bhh1,
                     const float* __restrict__ Wcih, const float* __restrict__ Wchh,
                     const float* __restrict__ bcih, const float* __restrict__ bchh,
                     const float* __restrict__ Wout, const float* __restrict__ bout,
                     float* __restrict__ out) {
    extern __shared__ float sm[];
    float* W0s  = sm;                      // 64 k  x 256  (Whh0; later Wchh)
    float* W1s  = W0s + HID * GATES;       // 128 k x 256  ([Wih1;Whh1])
    float* hbuf = W1s + 2 * HID * GATES;   // 128 rows x HS (0-63 h0, 64-127 h1)
    float* xcur = hbuf + 2 * HID * HS;     // 64
    float* wouts = xcur + MM;              // 64

    const int tid = threadIdx.x;
    const int mg  = tid & 7;
    const int up  = tid >> 3;
    const int ms1 = mg * 4;
    const int ms2 = 32 + mg * 4;
    const int w8  = up * 8;

    const int n0 = blockIdx.x * MM;
    const int b  = n0 >> 9;
    const int s0 = n0 & (SS - 1);
    const long xrow = (long)b * LL * SS + s0;

    // ---- stage weights (gate-interleaved, k-major): Wint[k][u*4+g] ----
    for (int idx = tid; idx < GATES * HID; idx += TH) {
        int jj = idx >> 6, k = idx & 63;
        int g = jj >> 6, u = jj & 63;
        int d = k * GATES + u * 4 + g;
        W0s[d] = Whh0[idx];
        W1s[d] = Wih1[idx];
        W1s[(HID + k) * GATES + u * 4 + g] = Whh1[idx];
    }
    for (int idx = tid; idx < 2 * HID * HS; idx += TH) hbuf[idx] = 0.f;
    if (tid < HID) wouts[tid] = Wout[tid];

    float w0g[2][4], b0g[2][4], b1g[2][4];
#pragma unroll
    for (int u = 0; u < 2; ++u)
#pragma unroll
        for (int g = 0; g < 4; ++g) {
            int row = g * 64 + 2 * up + u;
            w0g[u][g] = Wih0[row];
            b0g[u][g] = bih0[row] + bhh0[row];
            b1g[u][g] = bih1[row] + bhh1[row];
        }
    float c0[16], c1[16];
#pragma unroll
    for (int i = 0; i < 16; ++i) { c0[i] = 0.f; c1[i] = 0.f; }

    float* rowp0 = hbuf + (2 * up) * HS;
    float* rowp1 = hbuf + (HID + 2 * up) * HS;

    __syncthreads();

    // ================= encoder (2 barriers per step) =================
    for (int t = 0; t < LL; ++t) {
        float4 xA = __ldg((const float4*)(X + xrow + (long)t * SS + ms1));
        float4 xB = __ldg((const float4*)(X + xrow + (long)t * SS + ms2));

        u64t acc[2][4][4];
        // ---- layer 0: b0 + Whh0.h0_old + x*wih0 ----
        initacc(acc, b0g);
        matG(W0s + w8, hbuf + ms1, hbuf + ms2, acc);        // reads h0_old
        addx(acc, xA, xB, w0g);
        __syncthreads();                                    // bar1: h0_old reads done

        cellstore2(acc, c0, rowp0, ms1, ms2);               // writes h0_new (h0 rows)
        initacc(acc, b1g);
        matG(W1s + HID * GATES + w8, hbuf + HID * HS + ms1,
             hbuf + HID * HS + ms2, acc);                   // Whh1 . h1_old (h1 rows)
        __syncthreads();                                    // bar2: h0_new published,
                                                            //       h1_old reads done
        matG(W1s + w8, hbuf + ms1, hbuf + ms2, acc);        // Wih1 . h0_new (h0 rows)
        cellstore2(acc, c1, rowp1, ms1, ms2);               // writes h1_new (h1 rows)
    }

    // ================= decoder =================
    __syncthreads();                                        // h1_new visible
    for (int idx = tid; idx < GATES * HID; idx += TH) {     // W0s <- Wchh
        int jj = idx >> 6, k = idx & 63;
        int g = jj >> 6, u = jj & 63;
        W0s[k * GATES + u * 4 + g] = Wchh[idx];
    }
    float wcg[2][4], bcg[2][4];
#pragma unroll
    for (int u = 0; u < 2; ++u)
#pragma unroll
        for (int g = 0; g < 4; ++g) {
            int row = g * 64 + 2 * up + u;
            wcg[u][g] = Wcih[row];
            bcg[u][g] = bcih[row] + bchh[row];
        }
    if (tid < MM) xcur[tid] = X[xrow + (long)(LL - 1) * SS + tid];
    const float bo = bout[0];
    __syncthreads();

    for (int d = 0; d < HOR; ++d) {
        u64t acc[2][4][4];
        initacc(acc, bcg);
        float4 xA = *(const float4*)(xcur + ms1);
        float4 xB = *(const float4*)(xcur + ms2);
        matG(W0s + w8, hbuf + HID * HS + ms1, hbuf + HID * HS + ms2, acc);
        addx(acc, xA, xB, wcg);
        __syncthreads();                                    // h1_old + xcur reads done
        cellstore2(acc, c1, rowp1, ms1, ms2);               // h1_new
        __syncthreads();                                    // h1_new visible

        if (tid < MM) {
            float y = bo;
#pragma unroll 8
            for (int k = 0; k < HID; ++k)
                y = fmaf(wouts[k], hbuf[(HID + k) * HS + tid], y);
            out[((long)(b * HOR + d)) * SS + s0 + tid] = y;
            xcur[tid] = y;
        }
        __syncthreads();                                    // xcur visible
    }
}

extern "C" void kernel_launch(void* const* d_in, const int* in_sizes, int n_in,
                              void* d_out, int out_size) {
    const float* X    = (const float*)d_in[0];
    const float* Wih0 = (const float*)d_in[1];
    const float* Whh0 = (const float*)d_in[2];
    const float* bih0 = (const float*)d_in[3];
    const float* bhh0 = (const float*)d_in[4];
    const float* Wih1 = (const float*)d_in[5];
    const float* Whh1 = (const float*)d_in[6];
    const float* bih1 = (const float*)d_in[7];
    const float* bhh1 = (const float*)d_in[8];
    const float* Wcih = (const float*)d_in[9];
    const float* Wchh = (const float*)d_in[10];
    const float* bcih = (const float*)d_in[11];
    const float* bchh = (const float*)d_in[12];
    const float* Wout = (const float*)d_in[13];
    const float* bout = (const float*)d_in[14];

    const int smem_floats = HID * GATES
                          + 2 * HID * GATES
                          + 2 * HID * HS
                          + MM
                          + HID;
    const int smem_bytes = smem_floats * (int)sizeof(float);

    cudaFuncSetAttribute(sitewise_lstm_kernel,
                         cudaFuncAttributeMaxDynamicSharedMemorySize, smem_bytes);

    sitewise_lstm_kernel<<<NB, TH, smem_bytes>>>(
        X, Wih0, Whh0, bih0, bhh0, Wih1, Whh1, bih1, bhh1,
        Wcih, Wchh, bcih, bchh, Wout, bout, (float*)d_out);
}

// round 8
// speedup vs baseline: 1.7831x; 1.0003x over previous
#include <cuda_runtime.h>

// SiteWiseLSTM on GB300 (sm_103a) — round 6
// Identical to round 5 except activations use the HW tanh unit:
//   tanh(x)    -> tanh.approx.f32            (1 instr, 1 MUFU; was 6 instr/2 MUFU)
//   sigmoid(x) -> 0.5*tanh(0.5x) + 0.5       (3 instr, 1 MUFU; was 4 instr/2 MUFU)
// Cuts ~420 issue-slots/warp/step and halves MUFU pipe pressure; shortens the
// epilogue dependency chain ~2x. abs err of tanh.approx ~1e-4, recurrence is
// contractive -> expected rel_err ~1e-4 (budget 1e-3).

#define TH      256
#define MM      64      // samples per block
#define HID     64
#define GATES   256
#define LL      168
#define HOR     24
#define SS      512
#define NB      256     // 16384 / MM
#define HS      68      // h row stride in floats

typedef unsigned long long u64t;

__device__ __forceinline__ u64t pk2(float a, float b) {
    u64t r;
    asm("mov.b64 %0, {%1, %2};" : "=l"(r) : "f"(a), "f"(b));
    return r;
}
__device__ __forceinline__ void upk2(u64t v, float& a, float& b) {
    asm("mov.b64 {%0, %1}, %2;" : "=f"(a), "=f"(b) : "l"(v));
}
__device__ __forceinline__ void fma2(u64t& d, u64t a, u64t b) {
    asm("fma.rn.f32x2 %0, %1, %2, %0;" : "+l"(d) : "l"(a), "l"(b));
}
__device__ __forceinline__ float tanha(float x) {
    float y;
    asm("tanh.approx.f32 %0, %1;" : "=f"(y) : "f"(x));
    return y;
}
__device__ __forceinline__ float sigf(float x) {
    return fmaf(0.5f, tanha(0.5f * x), 0.5f);
}

// acc[u][g][p] += W[k][8up+4u+g] * h[k][samples], k = 0..63.
__device__ __forceinline__ void matG(const float* __restrict__ Ws,
                                     const float* __restrict__ hb1,
                                     const float* __restrict__ hb2,
                                     u64t acc[2][4][4]) {
#pragma unroll 4
    for (int k = 0; k < HID; ++k) {
        float4 wA = *(const float4*)(Ws + k * GATES);
        float4 wB = *(const float4*)(Ws + k * GATES + 4);
        ulonglong2 hA = *(const ulonglong2*)(hb1 + k * HS);
        ulonglong2 hB = *(const ulonglong2*)(hb2 + k * HS);
        u64t w2;
        w2 = pk2(wA.x, wA.x);
        fma2(acc[0][0][0], hA.x, w2); fma2(acc[0][0][1], hA.y, w2);
        fma2(acc[0][0][2], hB.x, w2); fma2(acc[0][0][3], hB.y, w2);
        w2 = pk2(wA.y, wA.y);
        fma2(acc[0][1][0], hA.x, w2); fma2(acc[0][1][1], hA.y, w2);
        fma2(acc[0][1][2], hB.x, w2); fma2(acc[0][1][3], hB.y, w2);
        w2 = pk2(wA.z, wA.z);
        fma2(acc[0][2][0], hA.x, w2); fma2(acc[0][2][1], hA.y, w2);
        fma2(acc[0][2][2], hB.x, w2); fma2(acc[0][2][3], hB.y, w2);
        w2 = pk2(wA.w, wA.w);
        fma2(acc[0][3][0], hA.x, w2); fma2(acc[0][3][1], hA.y, w2);
        fma2(acc[0][3][2], hB.x, w2); fma2(acc[0][3][3], hB.y, w2);
        w2 = pk2(wB.x, wB.x);
        fma2(acc[1][0][0], hA.x, w2); fma2(acc[1][0][1], hA.y, w2);
        fma2(acc[1][0][2], hB.x, w2); fma2(acc[1][0][3], hB.y, w2);
        w2 = pk2(wB.y, wB.y);
        fma2(acc[1][1][0], hA.x, w2); fma2(acc[1][1][1], hA.y, w2);
        fma2(acc[1][1][2], hB.x, w2); fma2(acc[1][1][3], hB.y, w2);
        w2 = pk2(wB.z, wB.z);
        fma2(acc[1][2][0], hA.x, w2); fma2(acc[1][2][1], hA.y, w2);
        fma2(acc[1][2][2], hB.x, w2); fma2(acc[1][2][3], hB.y, w2);
        w2 = pk2(wB.w, wB.w);
        fma2(acc[1][3][0], hA.x, w2); fma2(acc[1][3][1], hA.y, w2);
        fma2(acc[1][3][2], hB.x, w2); fma2(acc[1][3][3], hB.y, w2);
    }
}

__device__ __forceinline__ void addx(u64t acc[2][4][4], float4 xA, float4 xB,
                                     const float wg[2][4]) {
    u64t xp0 = pk2(xA.x, xA.y), xp1 = pk2(xA.z, xA.w);
    u64t xp2 = pk2(xB.x, xB.y), xp3 = pk2(xB.z, xB.w);
#pragma unroll
    for (int u = 0; u < 2; ++u)
#pragma unroll
        for (int g = 0; g < 4; ++g) {
            u64t w2 = pk2(wg[u][g], wg[u][g]);
            fma2(acc[u][g][0], xp0, w2); fma2(acc[u][g][1], xp1, w2);
            fma2(acc[u][g][2], xp2, w2); fma2(acc[u][g][3], xp3, w2);
        }
}

__device__ __forceinline__ void initacc(u64t acc[2][4][4], const float bg[2][4]) {
#pragma unroll
    for (int u = 0; u < 2; ++u)
#pragma unroll
        for (int g = 0; g < 4; ++g) {
            u64t bb = pk2(bg[u][g], bg[u][g]);
            acc[u][g][0] = bb; acc[u][g][1] = bb;
            acc[u][g][2] = bb; acc[u][g][3] = bb;
        }
}

// In-register LSTM cell for 2 units x 8 samples; writes h rows at ms1/ms2.
__device__ __forceinline__ void cellstore2(u64t acc[2][4][4], float* c,
                                           float* __restrict__ rowp,
                                           int ms1, int ms2) {
#pragma unroll
    for (int u = 0; u < 2; ++u) {
        float hv[8];
#pragma unroll
        for (int p = 0; p < 4; ++p) {
            float i0, i1, f0, f1, g0, g1, o0, o1;
            upk2(acc[u][0][p], i0, i1);
            upk2(acc[u][1][p], f0, f1);
            upk2(acc[u][2][p], g0, g1);
            upk2(acc[u][3][p], o0, o1);
            int ci = u * 8 + p * 2;
            float nc0 = sigf(f0) * c[ci]     + sigf(i0) * tanha(g0);
            float nc1 = sigf(f1) * c[ci + 1] + sigf(i1) * tanha(g1);
            c[ci] = nc0; c[ci + 1] = nc1;
            hv[p * 2]     = sigf(o0) * tanha(nc0);
            hv[p * 2 + 1] = sigf(o1) * tanha(nc1);
        }
        *(float4*)(rowp + u * HS + ms1) = make_float4(hv[0], hv[1], hv[2], hv[3]);
        *(float4*)(rowp + u * HS + ms2) = make_float4(hv[4], hv[5], hv[6], hv[7]);
    }
}

__global__ void __launch_bounds__(TH, 1)
sitewise_lstm_kernel(const float* __restrict__ X,
                     const float* __restrict__ Wih0, const float* __restrict__ Whh0,
                     const float* __restrict__ bih0, const float* __restrict__ bhh0,
                     const float* __restrict__ Wih1, const float* __restrict__ Whh1,
                     const float* __restrict__ bih1, const float* __restrict__ bhh1,
                     const float* __restrict__ Wcih, const float* __restrict__ Wchh,
                     const float* __restrict__ bcih, const float* __restrict__ bchh,
                     const float* __restrict__ Wout, const float* __restrict__ bout,
                     float* __restrict__ out) {
    extern __shared__ float sm[];
    float* W0s  = sm;                      // 64 k  x 256  (Whh0; later Wchh)
    float* W1s  = W0s + HID * GATES;       // 128 k x 256  ([Wih1;Whh1])
    float* hbuf = W1s + 2 * HID * GATES;   // 128 rows x HS (0-63 h0, 64-127 h1)
    float* xcur = hbuf + 2 * HID * HS;     // 64
    float* wouts = xcur + MM;              // 64

    const int tid = threadIdx.x;
    const int mg  = tid & 7;
    const int up  = tid >> 3;
    const int ms1 = mg * 4;
    const int ms2 = 32 + mg * 4;
    const int w8  = up * 8;

    const int n0 = blockIdx.x * MM;
    const int b  = n0 >> 9;
    const int s0 = n0 & (SS - 1);
    const long xrow = (long)b * LL * SS + s0;

    // ---- stage weights (gate-interleaved, k-major): Wint[k][u*4+g] ----
    for (int idx = tid; idx < GATES * HID; idx += TH) {
        int jj = idx >> 6, k = idx & 63;
        int g = jj >> 6, u = jj & 63;
        int d = k * GATES + u * 4 + g;
        W0s[d] = Whh0[idx];
        W1s[d] = Wih1[idx];
        W1s[(HID + k) * GATES + u * 4 + g] = Whh1[idx];
    }
    for (int idx = tid; idx < 2 * HID * HS; idx += TH) hbuf[idx] = 0.f;
    if (tid < HID) wouts[tid] = Wout[tid];

    float w0g[2][4], b0g[2][4], b1g[2][4];
#pragma unroll
    for (int u = 0; u < 2; ++u)
#pragma unroll
        for (int g = 0; g < 4; ++g) {
            int row = g * 64 + 2 * up + u;
            w0g[u][g] = Wih0[row];
            b0g[u][g] = bih0[row] + bhh0[row];
            b1g[u][g] = bih1[row] + bhh1[row];
        }
    float c0[16], c1[16];
#pragma unroll
    for (int i = 0; i < 16; ++i) { c0[i] = 0.f; c1[i] = 0.f; }

    float* rowp0 = hbuf + (2 * up) * HS;
    float* rowp1 = hbuf + (HID + 2 * up) * HS;

    __syncthreads();

    // ================= encoder (2 barriers per step) =================
    for (int t = 0; t < LL; ++t) {
        float4 xA = __ldg((const float4*)(X + xrow + (long)t * SS + ms1));
        float4 xB = __ldg((const float4*)(X + xrow + (long)t * SS + ms2));

        u64t acc[2][4][4];
        // ---- layer 0: b0 + Whh0.h0_old + x*wih0 ----
        initacc(acc, b0g);
        matG(W0s + w8, hbuf + ms1, hbuf + ms2, acc);        // reads h0_old
        addx(acc, xA, xB, w0g);
        __syncthreads();                                    // bar1: h0_old reads done

        cellstore2(acc, c0, rowp0, ms1, ms2);               // writes h0_new (h0 rows)
        initacc(acc, b1g);
        matG(W1s + HID * GATES + w8, hbuf + HID * HS + ms1,
             hbuf + HID * HS + ms2, acc);                   // Whh1 . h1_old (h1 rows)
        __syncthreads();                                    // bar2: h0_new published,
                                                            //       h1_old reads done
        matG(W1s + w8, hbuf + ms1, hbuf + ms2, acc);        // Wih1 . h0_new (h0 rows)
        cellstore2(acc, c1, rowp1, ms1, ms2);               // writes h1_new (h1 rows)
    }

    // ================= decoder =================
    __syncthreads();                                        // h1_new visible
    for (int idx = tid; idx < GATES * HID; idx += TH) {     // W0s <- Wchh
        int jj = idx >> 6, k = idx & 63;
        int g = jj >> 6, u = jj & 63;
        W0s[k * GATES + u * 4 + g] = Wchh[idx];
    }
    float wcg[2][4], bcg[2][4];
#pragma unroll
    for (int u = 0; u < 2; ++u)
#pragma unroll
        for (int g = 0; g < 4; ++g) {
            int row = g * 64 + 2 * up + u;
            wcg[u][g] = Wcih[row];
            bcg[u][g] = bcih[row] + bchh[row];
        }
    if (tid < MM) xcur[tid] = X[xrow + (long)(LL - 1) * SS + tid];
    const float bo = bout[0];
    __syncthreads();

    for (int d = 0; d < HOR; ++d) {
        u64t acc[2][4][4];
        initacc(acc, bcg);
        float4 xA = *(const float4*)(xcur + ms1);
        float4 xB = *(const float4*)(xcur + ms2);
        matG(W0s + w8, hbuf + HID * HS + ms1, hbuf + HID * HS + ms2, acc);
        addx(acc, xA, xB, wcg);
        __syncthreads();                                    // h1_old + xcur reads done
        cellstore2(acc, c1, rowp1, ms1, ms2);               // h1_new
        __syncthreads();                                    // h1_new visible

        if (tid < MM) {
            float y = bo;
#pragma unroll 8
            for (int k = 0; k < HID; ++k)
                y = fmaf(wouts[k], hbuf[(HID + k) * HS + tid], y);
            out[((long)(b * HOR + d)) * SS + s0 + tid] = y;
            xcur[tid] = y;
        }
        __syncthreads();                                    // xcur visible
    }
}

extern "C" void kernel_launch(void* const* d_in, const int* in_sizes, int n_in,
                              void* d_out, int out_size) {
    const float* X    = (const float*)d_in[0];
    const float* Wih0 = (const float*)d_in[1];
    const float* Whh0 = (const float*)d_in[2];
    const float* bih0 = (const float*)d_in[3];
    const float* bhh0 = (const float*)d_in[4];
    const float* Wih1 = (const float*)d_in[5];
    const float* Whh1 = (const float*)d_in[6];
    const float* bih1 = (const float*)d_in[7];
    const float* bhh1 = (const float*)d_in[8];
    const float* Wcih = (const float*)d_in[9];
    const float* Wchh = (const float*)d_in[10];
    const float* bcih = (const float*)d_in[11];
    const float* bchh = (const float*)d_in[12];
    const float* Wout = (const float*)d_in[13];
    const float* bout = (const float*)d_in[14];

    const int smem_floats = HID * GATES
                          + 2 * HID * GATES
                          + 2 * HID * HS
                          + MM
                          + HID;
    const int smem_bytes = smem_floats * (int)sizeof(float);

    cudaFuncSetAttribute(sitewise_lstm_kernel,
                         cudaFuncAttributeMaxDynamicSharedMemorySize, smem_bytes);

    sitewise_lstm_kernel<<<NB, TH, smem_bytes>>>(
        X, Wih0, Whh0, bih0, bhh0, Wih1, Whh1, bih1, bhh1,
        Wcih, Wchh, bcih, bchh, Wout, bout, (float*)d_out);
}